// round 7
// baseline (speedup 1.0000x reference)
#include <cuda_runtime.h>
#include <stdint.h>

#define NT 512
#define SAMP 4096
#define CAP 2048
#define FCAP 1024

// order-preserving float->uint key (ascending)
__device__ __forceinline__ uint32_t f2key(uint32_t u) {
    return (u & 0x80000000u) ? ~u : (u ^ 0x80000000u);
}
__device__ __forceinline__ float key2f(uint32_t s) {
    uint32_t u = (s & 0x80000000u) ? (s ^ 0x80000000u) : ~s;
    return __uint_as_float(u);
}

// Threefry-2x32, 20 rounds, key = (0, 42) == jax.random.key(42)
__device__ __forceinline__ void threefry42(uint32_t x0, uint32_t x1,
                                           uint32_t& o0, uint32_t& o1) {
    const uint32_t ks0 = 0u, ks1 = 42u, ks2 = 0u ^ 42u ^ 0x1BD11BDAu;
    x0 += ks0; x1 += ks1;
#define TF_R(r) { x0 += x1; x1 = (x1 << (r)) | (x1 >> (32 - (r))); x1 ^= x0; }
    TF_R(13) TF_R(15) TF_R(26) TF_R(6)   x0 += ks1; x1 += ks2 + 1u;
    TF_R(17) TF_R(29) TF_R(16) TF_R(24)  x0 += ks2; x1 += ks0 + 2u;
    TF_R(13) TF_R(15) TF_R(26) TF_R(6)   x0 += ks0; x1 += ks1 + 3u;
    TF_R(17) TF_R(29) TF_R(16) TF_R(24)  x0 += ks1; x1 += ks2 + 4u;
    TF_R(13) TF_R(15) TF_R(26) TF_R(6)   x0 += ks2; x1 += ks0 + 5u;
#undef TF_R
    o0 = x0; o1 = x1;
}

// JAX partitionable-threefry (default since 0.4.30) gumbel at flat index j.
// total < 2^32 so counter hi word = 0; 32-bit draw returns bits1 ^ bits2.
__device__ __forceinline__ float gumbel_at(uint32_t j) {
    uint32_t o0, o1;
    threefry42(0u, j, o0, o1);
    uint32_t bits = o0 ^ o1;
    float f = __uint_as_float((bits >> 9) | 0x3F800000u) - 1.0f;  // [0,1)
    const float tiny = 1.17549435e-38f;
    float u = fmaxf(tiny, f + tiny);   // == max(tiny, f*(maxval-tiny)+tiny) in fp32
    return -logf(-logf(u));
}

__global__ __launch_bounds__(NT)
void topk_sample_kernel(const float* __restrict__ logits,
                        const float* __restrict__ temp_p,
                        const int* __restrict__ k_p,
                        float* __restrict__ out,   // indices as float32
                        int V) {
    __shared__ uint32_t sh_hist[2048];
    __shared__ uint32_t sh_part[NT];
    __shared__ uint32_t sh_ckey[CAP];
    __shared__ int      sh_cidx[CAP];
    __shared__ float    sh_fval[FCAP];
    __shared__ int      sh_fidx[FCAP];
    __shared__ float    sh_rv[NT];
    __shared__ int      sh_ri[NT];
    __shared__ int sh_B, sh_cnt, sh_T2, sh_mf;
    __shared__ float sh_temp;

    const int b = blockIdx.x, tid = threadIdx.x, lane = tid & 31;
    const float* row = logits + (size_t)b * (size_t)V;
    if (tid == 0) sh_temp = temp_p[0];
    __syncthreads();
    const float temp = sh_temp;
    int k = k_p ? k_p[0] : 50;
    if (k < 1) k = 1;
    if (k > FCAP) k = FCAP;

    // ---- level-1: sample histogram over first SAMP real elements ----
    for (int i = tid; i < 2048; i += NT) sh_hist[i] = 0;
    __syncthreads();
    int ns = (SAMP < V) ? SAMP : V;
    for (int i = tid; i < ns; i += NT)
        atomicAdd(&sh_hist[f2key(__float_as_uint(row[i])) >> 21], 1u);
    __syncthreads();

    unsigned target = (unsigned)((k > 64) ? k : 64);
    if (target > (unsigned)ns) target = (unsigned)ns;
    sh_part[tid] = sh_hist[4*tid] + sh_hist[4*tid+1] + sh_hist[4*tid+2] + sh_hist[4*tid+3];
    __syncthreads();
    if (tid == 0) {
        unsigned cum = 0; int bin = 0;
        for (int g = NT - 1; g >= 0; --g) {
            unsigned p = sh_part[g];
            if (cum + p >= target) {
                for (int bb = 4*g + 3; bb >= 4*g; --bb) {
                    cum += sh_hist[bb];
                    if (cum >= target) { bin = bb; break; }
                }
                break;
            }
            cum += p;
        }
        sh_B = bin;
    }
    __syncthreads();
    int Bbin = sh_B;

    // ---- pass B: collect all elements with key-bin >= Bbin (ballot compaction) ----
    const int Vpad = ((V + NT - 1) / NT) * NT;
    for (int attempt = 0; attempt < 8; ++attempt) {
        __syncthreads();
        if (tid == 0) sh_cnt = 0;
        __syncthreads();
        for (int i = tid; i < Vpad; i += NT) {
            uint32_t s = 0; bool cand = false;
            if (i < V) {
                s = f2key(__float_as_uint(row[i]));
                cand = (int)(s >> 21) >= Bbin;
            }
            unsigned m = __ballot_sync(0xffffffffu, cand);
            if (m) {
                int leader = __ffs(m) - 1;
                int pos = 0;
                if (lane == leader) pos = atomicAdd(&sh_cnt, __popc(m));
                pos = __shfl_sync(0xffffffffu, pos, leader);
                if (cand) {
                    unsigned off = (unsigned)pos + (unsigned)__popc(m & ((1u << lane) - 1u));
                    if (off < CAP) { sh_ckey[off] = s; sh_cidx[off] = i; }
                }
            }
        }
        __syncthreads();
        if (sh_cnt <= CAP || Bbin >= 2047) break;
        Bbin++;               // pathological overflow: tighten and retry
    }
    int C = sh_cnt; if (C > CAP) C = CAP;

    // ---- level-2: exact histogram over candidates, 256 fine bins ----
    for (int i = tid; i < 256; i += NT) sh_hist[i] = 0;
    __syncthreads();
    for (int i = tid; i < C; i += NT) {
        uint32_t rel = sh_ckey[i] - ((uint32_t)Bbin << 21);
        uint32_t b2 = rel >> 13; if (b2 > 255u) b2 = 255u;
        atomicAdd(&sh_hist[b2], 1u);
    }
    __syncthreads();
    if (tid == 0) {
        unsigned cum = 0; int bin = 0;
        for (int bb = 255; bb >= 0; --bb) {
            cum += sh_hist[bb];
            if (cum >= (unsigned)k) { bin = bb; break; }
        }
        sh_T2 = bin;   // if C < k, stays 0 -> keep everything
    }
    __syncthreads();
    // one bin of margin below the cut so scaled-domain tie partners survive
    int T2 = sh_T2 - 1; if (T2 < 0) T2 = 0;

    // ---- compact final set F (bin2 >= T2); scaled value via IEEE div ----
    if (tid == 0) sh_mf = 0;
    __syncthreads();
    const int Cpad = ((C + NT - 1) / NT) * NT;
    for (int i = tid; i < Cpad; i += NT) {
        bool f = false; uint32_t s = 0; int idx = 0;
        if (i < C) {
            s = sh_ckey[i]; idx = sh_cidx[i];
            uint32_t rel = s - ((uint32_t)Bbin << 21);
            uint32_t b2 = rel >> 13; if (b2 > 255u) b2 = 255u;
            f = (int)b2 >= T2;
        }
        unsigned m = __ballot_sync(0xffffffffu, f);
        if (m) {
            int leader = __ffs(m) - 1;
            int pos = 0;
            if (lane == leader) pos = atomicAdd(&sh_mf, __popc(m));
            pos = __shfl_sync(0xffffffffu, pos, leader);
            if (f) {
                unsigned off = (unsigned)pos + (unsigned)__popc(m & ((1u << lane) - 1u));
                if (off < FCAP) {
                    sh_fval[off] = __fdiv_rn(key2f(s), temp);
                    sh_fidx[off] = idx;
                }
            }
        }
    }
    __syncthreads();
    int mF = sh_mf; if (mF > FCAP) mF = FCAP;

    // ---- exact rank (value desc, index asc ties) == lax.top_k selection;
    //      gumbel + argmax (first-max) over the k winners ----
    float bv = __int_as_float(0xff800000); int bi = 0x7fffffff;
    for (int i = tid; i < mF; i += NT) {
        float sci = sh_fval[i]; int idi = sh_fidx[i];
        int r = 0;
        for (int j = 0; j < mF; ++j) {
            float scj = sh_fval[j];
            r += (scj > sci) || (scj == sci && sh_fidx[j] < idi);
        }
        if (r < k) {
            float score = sci + gumbel_at((uint32_t)b * (uint32_t)V + (uint32_t)idi);
            if (score > bv || (score == bv && idi < bi)) { bv = score; bi = idi; }
        }
    }
    sh_rv[tid] = bv; sh_ri[tid] = bi;
    __syncthreads();
    for (int st = NT / 2; st > 0; st >>= 1) {
        if (tid < st) {
            float v2 = sh_rv[tid + st]; int i2 = sh_ri[tid + st];
            if (v2 > sh_rv[tid] || (v2 == sh_rv[tid] && i2 < sh_ri[tid])) {
                sh_rv[tid] = v2; sh_ri[tid] = i2;
            }
        }
        __syncthreads();
    }
    if (tid == 0) out[b] = (float)sh_ri[0];   // __output__ is float32
}

extern "C" void kernel_launch(void* const* d_in, const int* in_sizes, int n_in,
                              void* d_out, int out_size) {
    const float* logits = (const float*)d_in[0];
    const float* temp   = (const float*)d_in[1];
    const int*   kptr   = (n_in > 2) ? (const int*)d_in[2] : nullptr;

    int rows  = out_size;                       // 256
    int total = in_sizes[0];                    // B*V
    int V     = total / rows;                   // 50257

    topk_sample_kernel<<<rows, NT>>>(logits, temp, kptr, (float*)d_out, V);
}

// round 9
// speedup vs baseline: 1.4909x; 1.4909x over previous
#include <cuda_runtime.h>
#include <stdint.h>

#define NT 512
#define SAMP 4096
#define CAP 2048
#define FCAP 1024

// order-preserving float->uint key (ascending)
__device__ __forceinline__ uint32_t f2key(uint32_t u) {
    return (u & 0x80000000u) ? ~u : (u ^ 0x80000000u);
}
__device__ __forceinline__ float key2f(uint32_t s) {
    uint32_t u = (s & 0x80000000u) ? (s ^ 0x80000000u) : ~s;
    return __uint_as_float(u);
}

// Threefry-2x32, 20 rounds, key = (0, 42) == jax.random.key(42)
__device__ __forceinline__ void threefry42(uint32_t x0, uint32_t x1,
                                           uint32_t& o0, uint32_t& o1) {
    const uint32_t ks0 = 0u, ks1 = 42u, ks2 = 0u ^ 42u ^ 0x1BD11BDAu;
    x0 += ks0; x1 += ks1;
#define TF_R(r) { x0 += x1; x1 = (x1 << (r)) | (x1 >> (32 - (r))); x1 ^= x0; }
    TF_R(13) TF_R(15) TF_R(26) TF_R(6)   x0 += ks1; x1 += ks2 + 1u;
    TF_R(17) TF_R(29) TF_R(16) TF_R(24)  x0 += ks2; x1 += ks0 + 2u;
    TF_R(13) TF_R(15) TF_R(26) TF_R(6)   x0 += ks0; x1 += ks1 + 3u;
    TF_R(17) TF_R(29) TF_R(16) TF_R(24)  x0 += ks1; x1 += ks2 + 4u;
    TF_R(13) TF_R(15) TF_R(26) TF_R(6)   x0 += ks2; x1 += ks0 + 5u;
#undef TF_R
    o0 = x0; o1 = x1;
}

// JAX partitionable-threefry gumbel at flat index j (counter hi word = 0)
__device__ __forceinline__ float gumbel_at(uint32_t j) {
    uint32_t o0, o1;
    threefry42(0u, j, o0, o1);
    uint32_t bits = o0 ^ o1;
    float f = __uint_as_float((bits >> 9) | 0x3F800000u) - 1.0f;  // [0,1)
    const float tiny = 1.17549435e-38f;
    float u = fmaxf(tiny, f + tiny);
    return -logf(-logf(u));
}

__global__ __launch_bounds__(NT)
void topk_sample_kernel(const float* __restrict__ logits,
                        const float* __restrict__ temp_p,
                        const int* __restrict__ k_p,
                        float* __restrict__ out,   // indices as float32
                        int V) {
    __shared__ uint32_t sh_hist[2048];
    __shared__ uint32_t sh_part[NT];
    __shared__ uint32_t sh_ckey[CAP];
    __shared__ int      sh_cidx[CAP];
    __shared__ float    sh_fval[FCAP];
    __shared__ int      sh_fidx[FCAP];
    __shared__ float    sh_rv[NT];
    __shared__ int      sh_ri[NT];
    __shared__ int sh_B, sh_cnt, sh_T2, sh_mf;
    __shared__ float sh_temp;

    const int b = blockIdx.x, tid = threadIdx.x;
    const float* row = logits + (size_t)b * (size_t)V;
    if (tid == 0) sh_temp = temp_p[0];
    __syncthreads();
    const float temp = sh_temp;
    int k = k_p ? k_p[0] : 50;
    if (k < 1) k = 1;
    if (k > FCAP) k = FCAP;

    // ---- level-1: sample histogram over first SAMP real elements ----
    for (int i = tid; i < 2048; i += NT) sh_hist[i] = 0;
    __syncthreads();
    int ns = (SAMP < V) ? SAMP : V;
    for (int i = tid; i < ns; i += NT)
        atomicAdd(&sh_hist[f2key(__float_as_uint(row[i])) >> 21], 1u);
    __syncthreads();

    unsigned target = (unsigned)((k > 64) ? k : 64);
    if (target > (unsigned)ns) target = (unsigned)ns;
    sh_part[tid] = sh_hist[4*tid] + sh_hist[4*tid+1] + sh_hist[4*tid+2] + sh_hist[4*tid+3];
    __syncthreads();
    if (tid == 0) {
        unsigned cum = 0; int bin = 0;
        for (int g = NT - 1; g >= 0; --g) {
            unsigned p = sh_part[g];
            if (cum + p >= target) {
                for (int bb = 4*g + 3; bb >= 4*g; --bb) {
                    cum += sh_hist[bb];
                    if (cum >= target) { bin = bb; break; }
                }
                break;
            }
            cum += p;
        }
        sh_B = bin;
    }
    __syncthreads();
    int Bbin = sh_B;

    // ---- pass B: vectorized sweep; float-domain threshold; direct atomics ----
    // alignment prologue (rows are only 4B-aligned: V*4 % 16 != 0)
    const int pro0 = ((int)((16u - ((uint32_t)(uintptr_t)row & 15u)) & 15u)) >> 2;
    const int pro = (pro0 < V) ? pro0 : V;
    const float4* __restrict__ row4 = (const float4*)(row + pro);
    const int n4 = (V - pro) >> 2;
    const int tail0 = pro + (n4 << 2);

    for (int attempt = 0; attempt < 8; ++attempt) {
        __syncthreads();
        if (tid == 0) sh_cnt = 0;
        __syncthreads();
        const float thF = key2f((uint32_t)Bbin << 21);

        #define PUSH(xv, ix) do { \
            if ((xv) >= thF) { \
                int off = atomicAdd(&sh_cnt, 1); \
                if (off < CAP) { sh_ckey[off] = f2key(__float_as_uint(xv)); sh_cidx[off] = (ix); } \
            } } while (0)

        for (int i = tid; i < pro; i += NT) PUSH(row[i], i);
        #pragma unroll 4
        for (int i4 = tid; i4 < n4; i4 += NT) {
            float4 v = row4[i4];
            int base = pro + (i4 << 2);
            PUSH(v.x, base);
            PUSH(v.y, base + 1);
            PUSH(v.z, base + 2);
            PUSH(v.w, base + 3);
        }
        for (int i = tail0 + tid; i < V; i += NT) PUSH(row[i], i);
        #undef PUSH

        __syncthreads();
        if (sh_cnt <= CAP || Bbin >= 2047) break;
        Bbin++;               // pathological overflow: tighten and retry
    }
    int C = sh_cnt; if (C > CAP) C = CAP;

    // ---- level-2: exact histogram over candidates, 256 fine bins ----
    for (int i = tid; i < 256; i += NT) sh_hist[i] = 0;
    __syncthreads();
    for (int i = tid; i < C; i += NT) {
        uint32_t rel = sh_ckey[i] - ((uint32_t)Bbin << 21);
        uint32_t b2 = rel >> 13; if (b2 > 255u) b2 = 255u;
        atomicAdd(&sh_hist[b2], 1u);
    }
    __syncthreads();
    if (tid == 0) {
        unsigned cum = 0; int bin = 0;
        for (int bb = 255; bb >= 0; --bb) {
            cum += sh_hist[bb];
            if (cum >= (unsigned)k) { bin = bb; break; }
        }
        sh_T2 = bin;
    }
    __syncthreads();
    int T2 = sh_T2 - 1; if (T2 < 0) T2 = 0;   // margin bin for scaled-domain ties

    // ---- compact final set F (bin2 >= T2); scaled value via IEEE div ----
    if (tid == 0) sh_mf = 0;
    __syncthreads();
    for (int i = tid; i < C; i += NT) {
        uint32_t s = sh_ckey[i];
        uint32_t rel = s - ((uint32_t)Bbin << 21);
        uint32_t b2 = rel >> 13; if (b2 > 255u) b2 = 255u;
        if ((int)b2 >= T2) {
            int off = atomicAdd(&sh_mf, 1);
            if (off < FCAP) {
                sh_fval[off] = __fdiv_rn(key2f(s), temp);
                sh_fidx[off] = sh_cidx[i];
            }
        }
    }
    __syncthreads();
    int mF = sh_mf; if (mF > FCAP) mF = FCAP;

    // ---- exact rank (value desc, index asc ties) == lax.top_k selection;
    //      gumbel + argmax (first-max) over the k winners ----
    float bv = __int_as_float(0xff800000); int bi = 0x7fffffff;
    for (int i = tid; i < mF; i += NT) {
        float sci = sh_fval[i]; int idi = sh_fidx[i];
        int r = 0;
        for (int j = 0; j < mF; ++j) {
            float scj = sh_fval[j];
            r += (scj > sci) || (scj == sci && sh_fidx[j] < idi);
        }
        if (r < k) {
            float score = sci + gumbel_at((uint32_t)b * (uint32_t)V + (uint32_t)idi);
            if (score > bv || (score == bv && idi < bi)) { bv = score; bi = idi; }
        }
    }
    sh_rv[tid] = bv; sh_ri[tid] = bi;
    __syncthreads();
    for (int st = NT / 2; st > 0; st >>= 1) {
        if (tid < st) {
            float v2 = sh_rv[tid + st]; int i2 = sh_ri[tid + st];
            if (v2 > sh_rv[tid] || (v2 == sh_rv[tid] && i2 < sh_ri[tid])) {
                sh_rv[tid] = v2; sh_ri[tid] = i2;
            }
        }
        __syncthreads();
    }
    if (tid == 0) out[b] = (float)sh_ri[0];
}

extern "C" void kernel_launch(void* const* d_in, const int* in_sizes, int n_in,
                              void* d_out, int out_size) {
    const float* logits = (const float*)d_in[0];
    const float* temp   = (const float*)d_in[1];
    const int*   kptr   = (n_in > 2) ? (const int*)d_in[2] : nullptr;

    int rows  = out_size;                       // 256
    int total = in_sizes[0];                    // B*V
    int V     = total / rows;                   // 50257

    topk_sample_kernel<<<rows, NT>>>(logits, temp, kptr, (float*)d_out, V);
}

// round 10
// speedup vs baseline: 1.5004x; 1.0063x over previous
#include <cuda_runtime.h>
#include <stdint.h>

#define NT 512
#define SAMP 4096
#define CAP 2048
#define FCAP 1024

// order-preserving float->uint key (ascending)
__device__ __forceinline__ uint32_t f2key(uint32_t u) {
    return (u & 0x80000000u) ? ~u : (u ^ 0x80000000u);
}
__device__ __forceinline__ float key2f(uint32_t s) {
    uint32_t u = (s & 0x80000000u) ? (s ^ 0x80000000u) : ~s;
    return __uint_as_float(u);
}

// Threefry-2x32, 20 rounds, key = (0, 42) == jax.random.key(42)
__device__ __forceinline__ void threefry42(uint32_t x0, uint32_t x1,
                                           uint32_t& o0, uint32_t& o1) {
    const uint32_t ks0 = 0u, ks1 = 42u, ks2 = 0u ^ 42u ^ 0x1BD11BDAu;
    x0 += ks0; x1 += ks1;
#define TF_R(r) { x0 += x1; x1 = (x1 << (r)) | (x1 >> (32 - (r))); x1 ^= x0; }
    TF_R(13) TF_R(15) TF_R(26) TF_R(6)   x0 += ks1; x1 += ks2 + 1u;
    TF_R(17) TF_R(29) TF_R(16) TF_R(24)  x0 += ks2; x1 += ks0 + 2u;
    TF_R(13) TF_R(15) TF_R(26) TF_R(6)   x0 += ks0; x1 += ks1 + 3u;
    TF_R(17) TF_R(29) TF_R(16) TF_R(24)  x0 += ks1; x1 += ks2 + 4u;
    TF_R(13) TF_R(15) TF_R(26) TF_R(6)   x0 += ks2; x1 += ks0 + 5u;
#undef TF_R
    o0 = x0; o1 = x1;
}

// JAX partitionable-threefry gumbel at flat index j (counter hi word = 0)
__device__ __forceinline__ float gumbel_at(uint32_t j) {
    uint32_t o0, o1;
    threefry42(0u, j, o0, o1);
    uint32_t bits = o0 ^ o1;
    float f = __uint_as_float((bits >> 9) | 0x3F800000u) - 1.0f;  // [0,1)
    const float tiny = 1.17549435e-38f;
    float u = fmaxf(tiny, f + tiny);
    return -logf(-logf(u));
}

__global__ __launch_bounds__(NT)
void topk_sample_kernel(const float* __restrict__ logits,
                        const float* __restrict__ temp_p,
                        const int* __restrict__ k_p,
                        float* __restrict__ out,   // indices as float32
                        int V) {
    __shared__ uint32_t sh_hist[2048];
    __shared__ uint32_t sh_part[NT];
    __shared__ uint32_t sh_ckey[CAP];
    __shared__ int      sh_cidx[CAP];
    __shared__ float    sh_fval[FCAP];
    __shared__ int      sh_fidx[FCAP];
    __shared__ float    sh_rv[NT];
    __shared__ int      sh_ri[NT];
    __shared__ int sh_B, sh_cnt, sh_T2, sh_mf;
    __shared__ float sh_temp;

    const int b = blockIdx.x, tid = threadIdx.x;
    const float* row = logits + (size_t)b * (size_t)V;
    if (tid == 0) sh_temp = temp_p[0];
    __syncthreads();
    const float temp = sh_temp;
    int k = k_p ? k_p[0] : 50;
    if (k < 1) k = 1;
    if (k > FCAP) k = FCAP;

    // ---- level-1: sample histogram over first SAMP real elements ----
    for (int i = tid; i < 2048; i += NT) sh_hist[i] = 0;
    __syncthreads();
    int ns = (SAMP < V) ? SAMP : V;
    for (int i = tid; i < ns; i += NT)
        atomicAdd(&sh_hist[f2key(__float_as_uint(row[i])) >> 21], 1u);
    __syncthreads();

    unsigned target = (unsigned)((k > 64) ? k : 64);
    if (target > (unsigned)ns) target = (unsigned)ns;
    sh_part[tid] = sh_hist[4*tid] + sh_hist[4*tid+1] + sh_hist[4*tid+2] + sh_hist[4*tid+3];
    __syncthreads();
    if (tid == 0) {
        unsigned cum = 0; int bin = 0;
        for (int g = NT - 1; g >= 0; --g) {
            unsigned p = sh_part[g];
            if (cum + p >= target) {
                for (int bb = 4*g + 3; bb >= 4*g; --bb) {
                    cum += sh_hist[bb];
                    if (cum >= target) { bin = bb; break; }
                }
                break;
            }
            cum += p;
        }
        sh_B = bin;
    }
    __syncthreads();
    int Bbin = sh_B;

    // ---- pass B: batched vectorized sweep; float threshold; direct atomics ----
    const int pro0 = ((int)((16u - ((uint32_t)(uintptr_t)row & 15u)) & 15u)) >> 2;
    const int pro = (pro0 < V) ? pro0 : V;
    const float4* __restrict__ row4 = (const float4*)(row + pro);
    const int n4 = (V - pro) >> 2;
    const int tail0 = pro + (n4 << 2);

    for (int attempt = 0; attempt < 8; ++attempt) {
        __syncthreads();
        if (tid == 0) sh_cnt = 0;
        __syncthreads();
        const float thF = key2f((uint32_t)Bbin << 21);

        #define PUSH(xv, ix) do { \
            if ((xv) >= thF) { \
                int off = atomicAdd(&sh_cnt, 1); \
                if (off < CAP) { sh_ckey[off] = f2key(__float_as_uint(xv)); sh_cidx[off] = (ix); } \
            } } while (0)
        #define PUSH4(v, base) do { \
            PUSH((v).x, (base)); PUSH((v).y, (base)+1); \
            PUSH((v).z, (base)+2); PUSH((v).w, (base)+3); } while (0)

        for (int i = tid; i < pro; i += NT) PUSH(row[i], i);

        int i4 = tid;
        // main: 4 independent float4 loads issued before ANY processing
        for (; i4 + 3 * NT < n4; i4 += 4 * NT) {
            float4 v0 = row4[i4];
            float4 v1 = row4[i4 + NT];
            float4 v2 = row4[i4 + 2 * NT];
            float4 v3 = row4[i4 + 3 * NT];
            PUSH4(v0, pro + (i4 << 2));
            PUSH4(v1, pro + ((i4 + NT) << 2));
            PUSH4(v2, pro + ((i4 + 2 * NT) << 2));
            PUSH4(v3, pro + ((i4 + 3 * NT) << 2));
        }
        for (; i4 < n4; i4 += NT) {
            float4 v = row4[i4];
            PUSH4(v, pro + (i4 << 2));
        }
        for (int i = tail0 + tid; i < V; i += NT) PUSH(row[i], i);
        #undef PUSH4
        #undef PUSH

        __syncthreads();
        if (sh_cnt <= CAP || Bbin >= 2047) break;
        Bbin++;               // pathological overflow: tighten and retry
    }
    int C = sh_cnt; if (C > CAP) C = CAP;

    // ---- level-2: exact histogram over candidates, 256 fine bins ----
    for (int i = tid; i < 256; i += NT) sh_hist[i] = 0;
    __syncthreads();
    for (int i = tid; i < C; i += NT) {
        uint32_t rel = sh_ckey[i] - ((uint32_t)Bbin << 21);
        uint32_t b2 = rel >> 13; if (b2 > 255u) b2 = 255u;
        atomicAdd(&sh_hist[b2], 1u);
    }
    __syncthreads();
    if (tid == 0) {
        unsigned cum = 0; int bin = 0;
        for (int bb = 255; bb >= 0; --bb) {
            cum += sh_hist[bb];
            if (cum >= (unsigned)k) { bin = bb; break; }
        }
        sh_T2 = bin;
    }
    __syncthreads();
    int T2 = sh_T2 - 1; if (T2 < 0) T2 = 0;   // margin bin for scaled-domain ties

    // ---- compact final set F (bin2 >= T2); scaled value via IEEE div ----
    if (tid == 0) sh_mf = 0;
    __syncthreads();
    for (int i = tid; i < C; i += NT) {
        uint32_t s = sh_ckey[i];
        uint32_t rel = s - ((uint32_t)Bbin << 21);
        uint32_t b2 = rel >> 13; if (b2 > 255u) b2 = 255u;
        if ((int)b2 >= T2) {
            int off = atomicAdd(&sh_mf, 1);
            if (off < FCAP) {
                sh_fval[off] = __fdiv_rn(key2f(s), temp);
                sh_fidx[off] = sh_cidx[i];
            }
        }
    }
    __syncthreads();
    int mF = sh_mf; if (mF > FCAP) mF = FCAP;

    // ---- exact rank (value desc, index asc ties) == lax.top_k selection;
    //      gumbel + argmax (first-max) over the k winners ----
    float bv = __int_as_float(0xff800000); int bi = 0x7fffffff;
    for (int i = tid; i < mF; i += NT) {
        float sci = sh_fval[i]; int idi = sh_fidx[i];
        int r = 0;
        for (int j = 0; j < mF; ++j) {
            float scj = sh_fval[j];
            r += (scj > sci) || (scj == sci && sh_fidx[j] < idi);
        }
        if (r < k) {
            float score = sci + gumbel_at((uint32_t)b * (uint32_t)V + (uint32_t)idi);
            if (score > bv || (score == bv && idi < bi)) { bv = score; bi = idi; }
        }
    }
    sh_rv[tid] = bv; sh_ri[tid] = bi;
    __syncthreads();
    for (int st = NT / 2; st > 0; st >>= 1) {
        if (tid < st) {
            float v2 = sh_rv[tid + st]; int i2 = sh_ri[tid + st];
            if (v2 > sh_rv[tid] || (v2 == sh_rv[tid] && i2 < sh_ri[tid])) {
                sh_rv[tid] = v2; sh_ri[tid] = i2;
            }
        }
        __syncthreads();
    }
    if (tid == 0) out[b] = (float)sh_ri[0];
}

extern "C" void kernel_launch(void* const* d_in, const int* in_sizes, int n_in,
                              void* d_out, int out_size) {
    const float* logits = (const float*)d_in[0];
    const float* temp   = (const float*)d_in[1];
    const int*   kptr   = (n_in > 2) ? (const int*)d_in[2] : nullptr;

    int rows  = out_size;                       // 256
    int total = in_sizes[0];                    // B*V
    int V     = total / rows;                   // 50257

    topk_sample_kernel<<<rows, NT>>>(logits, temp, kptr, (float*)d_out, V);
}

// round 13
// speedup vs baseline: 1.5710x; 1.0471x over previous
#include <cuda_runtime.h>
#include <stdint.h>

#define NT 512
#define SAMP 4096
#define CAP 2048
#define FCAP 1024

// order-preserving float->uint key (ascending)
__device__ __forceinline__ uint32_t f2key(uint32_t u) {
    return (u & 0x80000000u) ? ~u : (u ^ 0x80000000u);
}
__device__ __forceinline__ float key2f(uint32_t s) {
    uint32_t u = (s & 0x80000000u) ? (s ^ 0x80000000u) : ~s;
    return __uint_as_float(u);
}

// Threefry-2x32, 20 rounds, key = (0, 42) == jax.random.key(42)
__device__ __forceinline__ void threefry42(uint32_t x0, uint32_t x1,
                                           uint32_t& o0, uint32_t& o1) {
    const uint32_t ks0 = 0u, ks1 = 42u, ks2 = 0u ^ 42u ^ 0x1BD11BDAu;
    x0 += ks0; x1 += ks1;
#define TF_R(r) { x0 += x1; x1 = (x1 << (r)) | (x1 >> (32 - (r))); x1 ^= x0; }
    TF_R(13) TF_R(15) TF_R(26) TF_R(6)   x0 += ks1; x1 += ks2 + 1u;
    TF_R(17) TF_R(29) TF_R(16) TF_R(24)  x0 += ks2; x1 += ks0 + 2u;
    TF_R(13) TF_R(15) TF_R(26) TF_R(6)   x0 += ks0; x1 += ks1 + 3u;
    TF_R(17) TF_R(29) TF_R(16) TF_R(24)  x0 += ks1; x1 += ks2 + 4u;
    TF_R(13) TF_R(15) TF_R(26) TF_R(6)   x0 += ks2; x1 += ks0 + 5u;
#undef TF_R
    o0 = x0; o1 = x1;
}

// JAX partitionable-threefry gumbel at flat index j (counter hi word = 0)
__device__ __forceinline__ float gumbel_at(uint32_t j) {
    uint32_t o0, o1;
    threefry42(0u, j, o0, o1);
    uint32_t bits = o0 ^ o1;
    float f = __uint_as_float((bits >> 9) | 0x3F800000u) - 1.0f;  // [0,1)
    const float tiny = 1.17549435e-38f;
    float u = fmaxf(tiny, f + tiny);
    return -logf(-logf(u));
}

#define LDG4(v, p) \
    asm volatile("ld.global.nc.v4.f32 {%0,%1,%2,%3}, [%4];" \
        : "=f"((v).x), "=f"((v).y), "=f"((v).z), "=f"((v).w) : "l"(p))

__global__ __launch_bounds__(NT, 2)
void topk_sample_kernel(const float* __restrict__ logits,
                        const float* __restrict__ temp_p,
                        const int* __restrict__ k_p,
                        float* __restrict__ out,   // indices as float32
                        int V) {
    __shared__ uint32_t sh_hist[2048];
    __shared__ uint32_t sh_part[NT];
    __shared__ uint32_t sh_ckey[CAP];
    __shared__ int      sh_cidx[CAP];
    __shared__ float    sh_fval[FCAP];
    __shared__ int      sh_fidx[FCAP];
    __shared__ float    sh_rv[NT];
    __shared__ int      sh_ri[NT];
    __shared__ int sh_B, sh_cnt, sh_T2, sh_mf, sh_g;
    __shared__ float sh_temp;

    const int b = blockIdx.x, tid = threadIdx.x;
    const float* row = logits + (size_t)b * (size_t)V;
    if (tid == 0) sh_temp = temp_p[0];
    __syncthreads();
    const float temp = sh_temp;
    int k = k_p ? k_p[0] : 50;
    if (k < 1) k = 1;
    if (k > FCAP) k = FCAP;

    // ---- level-1: sample histogram over first SAMP real elements ----
    for (int i = tid; i < 2048; i += NT) sh_hist[i] = 0;
    __syncthreads();
    int ns = (SAMP < V) ? SAMP : V;
    for (int i = tid; i < ns; i += NT)
        atomicAdd(&sh_hist[f2key(__float_as_uint(row[i])) >> 21], 1u);
    __syncthreads();

    unsigned target = (unsigned)((k > 64) ? k : 64);
    if (target > (unsigned)ns) target = (unsigned)ns;
    // group sums (4 bins/group) then parallel suffix scan
    sh_part[tid] = sh_hist[4*tid] + sh_hist[4*tid+1] + sh_hist[4*tid+2] + sh_hist[4*tid+3];
    if (tid == 0) sh_g = 0;
    __syncthreads();
    for (int d = 1; d < NT; d <<= 1) {
        uint32_t add = (tid + d < NT) ? sh_part[tid + d] : 0u;
        __syncthreads();
        sh_part[tid] += add;
        __syncthreads();
    }
    // sh_part[g] = count of samples in groups >= g (non-increasing)
    if (sh_part[tid] >= target) atomicMax(&sh_g, tid);
    __syncthreads();
    if (tid == 0) {
        int g = sh_g;
        unsigned cum = (g + 1 < NT) ? sh_part[g + 1] : 0u;
        int bin = 4 * g;
        for (int bb = 4*g + 3; bb >= 4*g; --bb) {
            cum += sh_hist[bb];
            if (cum >= target) { bin = bb; break; }
        }
        sh_B = bin;
    }
    __syncthreads();
    int Bbin = sh_B;

    // ---- pass B: forced-batch vectorized sweep; float threshold ----
    const int pro0 = ((int)((16u - ((uint32_t)(uintptr_t)row & 15u)) & 15u)) >> 2;
    const int pro = (pro0 < V) ? pro0 : V;
    const float4* __restrict__ row4 = (const float4*)(row + pro);
    const int n4 = (V - pro) >> 2;
    const int tail0 = pro + (n4 << 2);

    for (int attempt = 0; attempt < 8; ++attempt) {
        __syncthreads();
        if (tid == 0) sh_cnt = 0;
        __syncthreads();
        const float thF = key2f((uint32_t)Bbin << 21);

        #define PUSH(xv, ix) do { \
            if ((xv) >= thF) { \
                int off = atomicAdd(&sh_cnt, 1); \
                if (off < CAP) { sh_ckey[off] = f2key(__float_as_uint(xv)); sh_cidx[off] = (ix); } \
            } } while (0)
        #define PUSH4(v, base) do { \
            PUSH((v).x, (base)); PUSH((v).y, (base)+1); \
            PUSH((v).z, (base)+2); PUSH((v).w, (base)+3); } while (0)

        for (int i = tid; i < pro; i += NT) PUSH(row[i], i);

        int i4 = tid;
        for (; i4 + 3 * NT < n4; i4 += 4 * NT) {
            float4 v0, v1, v2, v3;
            LDG4(v0, row4 + i4);
            LDG4(v1, row4 + i4 + NT);
            LDG4(v2, row4 + i4 + 2 * NT);
            LDG4(v3, row4 + i4 + 3 * NT);
            PUSH4(v0, pro + (i4 << 2));
            PUSH4(v1, pro + ((i4 + NT) << 2));
            PUSH4(v2, pro + ((i4 + 2 * NT) << 2));
            PUSH4(v3, pro + ((i4 + 3 * NT) << 2));
        }
        for (; i4 < n4; i4 += NT) {
            float4 v;
            LDG4(v, row4 + i4);
            PUSH4(v, pro + (i4 << 2));
        }
        for (int i = tail0 + tid; i < V; i += NT) PUSH(row[i], i);
        #undef PUSH4
        #undef PUSH

        __syncthreads();
        if (sh_cnt <= CAP || Bbin >= 2047) break;
        Bbin++;               // pathological overflow: tighten and retry
    }
    int C = sh_cnt; if (C > CAP) C = CAP;

    // ---- level-2: exact histogram over candidates, 256 fine bins ----
    for (int i = tid; i < 256; i += NT) sh_hist[i] = 0;
    __syncthreads();
    for (int i = tid; i < C; i += NT) {
        uint32_t rel = sh_ckey[i] - ((uint32_t)Bbin << 21);
        uint32_t b2 = rel >> 13; if (b2 > 255u) b2 = 255u;
        atomicAdd(&sh_hist[b2], 1u);
    }
    if (tid == 0) sh_T2 = 0;
    __syncthreads();
    // parallel suffix scan over 256 bins (threads 0..255)
    if (tid < 256) sh_part[tid] = sh_hist[tid];
    __syncthreads();
    for (int d = 1; d < 256; d <<= 1) {
        uint32_t add = 0;
        if (tid < 256 && tid + d < 256) add = sh_part[tid + d];
        __syncthreads();
        if (tid < 256) sh_part[tid] += add;
        __syncthreads();
    }
    if (tid < 256 && sh_part[tid] >= (unsigned)k) atomicMax(&sh_T2, tid);
    __syncthreads();
    int T2 = sh_T2 - 1; if (T2 < 0) T2 = 0;   // margin bin for scaled-domain ties

    // ---- compact final set F (bin2 >= T2); scaled value via IEEE div ----
    if (tid == 0) sh_mf = 0;
    __syncthreads();
    for (int i = tid; i < C; i += NT) {
        uint32_t s = sh_ckey[i];
        uint32_t rel = s - ((uint32_t)Bbin << 21);
        uint32_t b2 = rel >> 13; if (b2 > 255u) b2 = 255u;
        if ((int)b2 >= T2) {
            int off = atomicAdd(&sh_mf, 1);
            if (off < FCAP) {
                sh_fval[off] = __fdiv_rn(key2f(s), temp);
                sh_fidx[off] = sh_cidx[i];
            }
        }
    }
    __syncthreads();
    int mF = sh_mf; if (mF > FCAP) mF = FCAP;

    // ---- exact rank (value desc, index asc ties) == lax.top_k selection;
    //      gumbel + argmax (first-max) over the k winners ----
    float bv = __int_as_float(0xff800000); int bi = 0x7fffffff;
    for (int i = tid; i < mF; i += NT) {
        float sci = sh_fval[i]; int idi = sh_fidx[i];
        int r = 0;
        for (int j = 0; j < mF; ++j) {
            float scj = sh_fval[j];
            r += (scj > sci) || (scj == sci && sh_fidx[j] < idi);
        }
        if (r < k) {
            float score = sci + gumbel_at((uint32_t)b * (uint32_t)V + (uint32_t)idi);
            if (score > bv || (score == bv && idi < bi)) { bv = score; bi = idi; }
        }
    }
    sh_rv[tid] = bv; sh_ri[tid] = bi;
    __syncthreads();
    for (int st = NT / 2; st > 0; st >>= 1) {
        if (tid < st) {
            float v2 = sh_rv[tid + st]; int i2 = sh_ri[tid + st];
            if (v2 > sh_rv[tid] || (v2 == sh_rv[tid] && i2 < sh_ri[tid])) {
                sh_rv[tid] = v2; sh_ri[tid] = i2;
            }
        }
        __syncthreads();
    }
    if (tid == 0) out[b] = (float)sh_ri[0];
}

extern "C" void kernel_launch(void* const* d_in, const int* in_sizes, int n_in,
                              void* d_out, int out_size) {
    const float* logits = (const float*)d_in[0];
    const float* temp   = (const float*)d_in[1];
    const int*   kptr   = (n_in > 2) ? (const int*)d_in[2] : nullptr;

    int rows  = out_size;                       // 256
    int total = in_sizes[0];                    // B*V
    int V     = total / rows;                   // 50257

    topk_sample_kernel<<<rows, NT>>>(logits, temp, kptr, (float*)d_out, V);
}